// round 1
// baseline (speedup 1.0000x reference)
#include <cuda_runtime.h>
#include <math.h>

// Problem constants
#define Bn   4
#define Tn   4096
#define Dn   1024
#define Hn   16
#define HD   64
#define BH   64            // Bn*Hn
#define CHUNK 128
#define NCH  32            // Tn/CHUNK
#define Mn   16384         // Bn*Tn

// Scratch (device globals; no allocations allowed)
static __device__ float    g_q[(size_t)BH * Tn * HD];   // roped Q, [bh, t, 64]
static __device__ float    g_k[(size_t)BH * Tn * HD];   // roped K
static __device__ float    g_v[(size_t)BH * Tn * HD];   // V
static __device__ float    g_xo[(size_t)Mn * Dn];       // unsorted attn output, [b*T+t, 1024]
static __device__ unsigned g_keys[BH * Tn];             // (bucket<<12)|t
static __device__ int      g_sidx[BH * Tn];             // sorted_idx per (bh)

// ---------------------------------------------------------------------------
// GEMM 1: qkv = x @ W_attn + b_attn, scattered straight into head layout.
// M=16384, N=3072, K=1024. 128x128 tile, BK=8, 256 threads, 8x8 microtile.
// ---------------------------------------------------------------------------
__global__ __launch_bounds__(256) void gemm_qkv_kernel(
    const float* __restrict__ X, const float* __restrict__ W,
    const float* __restrict__ bias)
{
    const int K = Dn, N = 3 * Dn;
    __shared__ float As[8][128];
    __shared__ float Bs[8][128];
    int tid = threadIdx.x;
    int bm = blockIdx.y * 128;
    int bn = blockIdx.x * 128;
    int arow = tid >> 1,  acol = (tid & 1) << 2;
    int brow = tid >> 5,  bcol = (tid & 31) << 2;
    const float* Ap = X + (size_t)(bm + arow) * K + acol;
    const float* Bp = W + (size_t)brow * N + bn + bcol;
    int ty = tid >> 4, tx = tid & 15;

    float acc[8][8];
#pragma unroll
    for (int i = 0; i < 8; i++)
#pragma unroll
        for (int j = 0; j < 8; j++) acc[i][j] = 0.f;

    for (int k0 = 0; k0 < K; k0 += 8) {
        float4 a4 = *(const float4*)Ap;
        float4 b4 = *(const float4*)Bp;
        As[acol + 0][arow] = a4.x;
        As[acol + 1][arow] = a4.y;
        As[acol + 2][arow] = a4.z;
        As[acol + 3][arow] = a4.w;
        *(float4*)&Bs[brow][bcol] = b4;
        __syncthreads();
#pragma unroll
        for (int kk = 0; kk < 8; kk++) {
            float a[8], b[8];
            *(float4*)&a[0] = *(const float4*)&As[kk][ty * 8];
            *(float4*)&a[4] = *(const float4*)&As[kk][ty * 8 + 4];
            *(float4*)&b[0] = *(const float4*)&Bs[kk][tx * 8];
            *(float4*)&b[4] = *(const float4*)&Bs[kk][tx * 8 + 4];
#pragma unroll
            for (int i = 0; i < 8; i++)
#pragma unroll
                for (int j = 0; j < 8; j++) acc[i][j] += a[i] * b[j];
        }
        __syncthreads();
        Ap += 8;
        Bp += (size_t)8 * N;
    }

    // Epilogue: scatter into q/k/v head layout [bh, t, 64]
    int n0    = bn + tx * 8;        // 8 consecutive cols, same which/head
    int which = n0 >> 10;
    int dd0   = n0 & 1023;
    int h     = dd0 >> 6;
    int j0    = dd0 & 63;
    float* dst = (which == 0) ? g_q : (which == 1 ? g_k : g_v);
    float bb[8];
#pragma unroll
    for (int j = 0; j < 8; j++) bb[j] = bias[n0 + j];
#pragma unroll
    for (int i = 0; i < 8; i++) {
        int m = bm + ty * 8 + i;
        int b = m >> 12;            // m / T
        int t = m & 4095;
        float* row = dst + (((size_t)(b * Hn + h) * Tn) + t) * HD + j0;
#pragma unroll
        for (int j = 0; j < 8; j++) row[j] = acc[i][j] + bb[j];
    }
}

// ---------------------------------------------------------------------------
// RoPE on q and k in-place. One thread per (bh,t, even/odd pair).
// Matches JAX: angle(d) = t * (1/10000^((d&31)/32)); note d0,d1 use
// DIFFERENT angles (interleaved rotate with concatenated freqs).
// ---------------------------------------------------------------------------
__global__ void rope_kernel()
{
    int idx = blockIdx.x * blockDim.x + threadIdx.x;    // over BH*T*32
    if (idx >= BH * Tn * 32) return;
    int p  = idx & 31;
    int rt = idx >> 5;                                  // bh*T + t
    int t  = rt & 4095;
    int d0 = p * 2, d1 = p * 2 + 1;
    float e0 = (float)(d0 & 31) * (1.0f / 32.0f);
    float e1 = (float)(d1 & 31) * (1.0f / 32.0f);
    float inv0 = 1.0f / powf(10000.0f, e0);
    float inv1 = 1.0f / powf(10000.0f, e1);
    float a0 = (float)t * inv0, a1 = (float)t * inv1;
    float s0, c0, s1, c1;
    sincosf(a0, &s0, &c0);
    sincosf(a1, &s1, &c1);
    size_t base = (size_t)rt * HD;
    float q0 = g_q[base + d0], q1 = g_q[base + d1];
    g_q[base + d0] = q0 * c0 - q1 * s0;
    g_q[base + d1] = q1 * c1 + q0 * s1;
    float k0 = g_k[base + d0], k1 = g_k[base + d1];
    g_k[base + d0] = k0 * c0 - k1 * s0;
    g_k[base + d1] = k1 * c1 + k0 * s1;
}

// ---------------------------------------------------------------------------
// Bucket: proj = q . R[:,0,:], bucket = argmax over [proj, -proj] (first max).
// Composite key (bucket<<12)|t makes bitonic sort == stable argsort.
// ---------------------------------------------------------------------------
__global__ __launch_bounds__(128) void bucket_kernel(const float* __restrict__ R)
{
    __shared__ float Rs[64 * 32];                        // hash 0 slice
    int tid = threadIdx.x;
    for (int i = tid; i < 2048; i += 128) {
        int d = i >> 5, m = i & 31;
        Rs[i] = R[d * 64 + m];                           // R[d, 0, m]
    }
    __syncthreads();

    int idx = blockIdx.x * 128 + tid;                    // bh*T + t
    float q[64];
    const float* qp = &g_q[(size_t)idx * HD];
#pragma unroll
    for (int l = 0; l < 16; l++) *(float4*)&q[l * 4] = *(const float4*)&qp[l * 4];

    float proj[32];
    for (int m = 0; m < 32; m++) {
        float s = 0.f;
#pragma unroll
        for (int d = 0; d < 64; d++) s += q[d] * Rs[d * 32 + m];
        proj[m] = s;
    }
    float best = -1e30f; int bi = 0;
#pragma unroll
    for (int i = 0; i < 64; i++) {
        float v = (i < 32) ? proj[i] : -proj[i - 32];
        if (v > best) { best = v; bi = i; }
    }
    g_keys[idx] = ((unsigned)bi << 12) | (unsigned)(idx & 4095);
}

// ---------------------------------------------------------------------------
// Per-(bh) bitonic sort of 4096 composite keys in SMEM. Keys are distinct, so
// the result is exactly the stable sort JAX's argsort produces.
// ---------------------------------------------------------------------------
__global__ __launch_bounds__(1024) void sort_kernel()
{
    __shared__ unsigned s[4096];
    int bh = blockIdx.x, tid = threadIdx.x;
    for (int i = tid; i < 4096; i += 1024) s[i] = g_keys[bh * 4096 + i];
    __syncthreads();
    for (int k = 2; k <= 4096; k <<= 1) {
        for (int j = k >> 1; j > 0; j >>= 1) {
            for (int i = tid; i < 4096; i += 1024) {
                int ixj = i ^ j;
                if (ixj > i) {
                    unsigned a = s[i], b = s[ixj];
                    bool up = (i & k) == 0;
                    if ((a > b) == up) { s[i] = b; s[ixj] = a; }
                }
            }
            __syncthreads();
        }
    }
    for (int i = tid; i < 4096; i += 1024)
        g_sidx[bh * 4096 + i] = (int)(s[i] & 4095u);
}

// ---------------------------------------------------------------------------
// Fused gather + chunked softmax attention + unsort-scatter.
// One block per (bh, chunk): gathers K/V rows via sorted_idx into SMEM,
// each of 128 threads owns one query row (Q in registers), stages its score
// row in padded SMEM, and scatters O directly to the unsorted [B,T,D] buffer.
// ---------------------------------------------------------------------------
#define ATTN_SMEM ((8192 + 8192 + 128 * 129) * 4)

__global__ __launch_bounds__(128) void attn_kernel()
{
    extern __shared__ float sm[];
    float* Ks = sm;                 // [128][64]
    float* Vs = sm + 8192;          // [128][64]
    float* Ss = sm + 16384;         // [128][129] padded
    __shared__ int sidx_s[128];

    int bc = blockIdx.x;
    int bh = bc >> 5;               // / NCH
    int c  = bc & 31;
    int p0 = c * 128;
    int tid = threadIdx.x;
    const int rowbase = bh * Tn;

    sidx_s[tid] = g_sidx[rowbase + p0 + tid];
    __syncthreads();

    // Gather K and V chunk rows through the sort permutation
    for (int i = tid; i < 128 * 16; i += 128) {
        int r = i >> 4, l = (i & 15) * 4;
        size_t src = ((size_t)(rowbase + sidx_s[r])) * HD + l;
        *(float4*)&Ks[r * 64 + l] = *(const float4*)&g_k[src];
        *(float4*)&Vs[r * 64 + l] = *(const float4*)&g_v[src];
    }
    __syncthreads();

    int r  = tid;
    int si = sidx_s[r];
    float qr[64];
    {
        const float* qp = &g_q[((size_t)(rowbase + si)) * HD];
#pragma unroll
        for (int l = 0; l < 16; l++) *(float4*)&qr[l * 4] = *(const float4*)&qp[l * 4];
    }

    // Pass 1: S row = Q . K^T / 8, track max
    float mx = -1e30f;
    for (int j = 0; j < 128; j++) {
        const float* kp = &Ks[j * 64];
        float s0 = 0.f, s1 = 0.f, s2 = 0.f, s3 = 0.f;
#pragma unroll
        for (int d = 0; d < 64; d += 4) {
            float4 k4 = *(const float4*)&kp[d];
            s0 += qr[d + 0] * k4.x;
            s1 += qr[d + 1] * k4.y;
            s2 += qr[d + 2] * k4.z;
            s3 += qr[d + 3] * k4.w;
        }
        float s = (s0 + s1 + s2 + s3) * 0.125f;
        Ss[r * 129 + j] = s;
        mx = fmaxf(mx, s);
    }

    // Softmax weights
    float sum = 0.f;
#pragma unroll 4
    for (int j = 0; j < 128; j++) {
        float e = __expf(Ss[r * 129 + j] - mx);
        Ss[r * 129 + j] = e;
        sum += e;
    }
    float inv = 1.0f / sum;

    // Pass 2: O = P V
    float o[64];
#pragma unroll
    for (int d = 0; d < 64; d++) o[d] = 0.f;
    for (int j = 0; j < 128; j++) {
        float p = Ss[r * 129 + j];
        const float* vp = &Vs[j * 64];
#pragma unroll
        for (int d = 0; d < 64; d += 4) {
            float4 v4 = *(const float4*)&vp[d];
            o[d + 0] += p * v4.x;
            o[d + 1] += p * v4.y;
            o[d + 2] += p * v4.z;
            o[d + 3] += p * v4.w;
        }
    }

    // Unsort-scatter straight into [B, T, D] layout for the output GEMM
    int b = bh >> 4, h = bh & 15;
    float* op = &g_xo[((size_t)(b * Tn + si)) * Dn + h * HD];
#pragma unroll
    for (int l = 0; l < 16; l++) {
        float4 v4 = make_float4(o[l * 4 + 0] * inv, o[l * 4 + 1] * inv,
                                o[l * 4 + 2] * inv, o[l * 4 + 3] * inv);
        *(float4*)&op[l * 4] = v4;
    }
}

// ---------------------------------------------------------------------------
// GEMM 2: out = g_xo @ W_proj + b_proj.  M=16384, N=1024, K=1024.
// ---------------------------------------------------------------------------
__global__ __launch_bounds__(256) void gemm_out_kernel(
    const float* __restrict__ W, const float* __restrict__ bias,
    float* __restrict__ C)
{
    const int K = Dn, N = Dn;
    __shared__ float As[8][128];
    __shared__ float Bs[8][128];
    int tid = threadIdx.x;
    int bm = blockIdx.y * 128;
    int bn = blockIdx.x * 128;
    int arow = tid >> 1,  acol = (tid & 1) << 2;
    int brow = tid >> 5,  bcol = (tid & 31) << 2;
    const float* Ap = g_xo + (size_t)(bm + arow) * K + acol;
    const float* Bp = W + (size_t)brow * N + bn + bcol;
    int ty = tid >> 4, tx = tid & 15;

    float acc[8][8];
#pragma unroll
    for (int i = 0; i < 8; i++)
#pragma unroll
        for (int j = 0; j < 8; j++) acc[i][j] = 0.f;

    for (int k0 = 0; k0 < K; k0 += 8) {
        float4 a4 = *(const float4*)Ap;
        float4 b4 = *(const float4*)Bp;
        As[acol + 0][arow] = a4.x;
        As[acol + 1][arow] = a4.y;
        As[acol + 2][arow] = a4.z;
        As[acol + 3][arow] = a4.w;
        *(float4*)&Bs[brow][bcol] = b4;
        __syncthreads();
#pragma unroll
        for (int kk = 0; kk < 8; kk++) {
            float a[8], b[8];
            *(float4*)&a[0] = *(const float4*)&As[kk][ty * 8];
            *(float4*)&a[4] = *(const float4*)&As[kk][ty * 8 + 4];
            *(float4*)&b[0] = *(const float4*)&Bs[kk][tx * 8];
            *(float4*)&b[4] = *(const float4*)&Bs[kk][tx * 8 + 4];
#pragma unroll
            for (int i = 0; i < 8; i++)
#pragma unroll
                for (int j = 0; j < 8; j++) acc[i][j] += a[i] * b[j];
        }
        __syncthreads();
        Ap += 8;
        Bp += (size_t)8 * N;
    }

    float bb[8];
#pragma unroll
    for (int j = 0; j < 8; j++) bb[j] = bias[bn + tx * 8 + j];
#pragma unroll
    for (int i = 0; i < 8; i++) {
        int m = bm + ty * 8 + i;
        float* row = C + (size_t)m * N + bn + tx * 8;
#pragma unroll
        for (int j = 0; j < 8; j++) row[j] = acc[i][j] + bb[j];
    }
}

// ---------------------------------------------------------------------------
extern "C" void kernel_launch(void* const* d_in, const int* in_sizes, int n_in,
                              void* d_out, int out_size)
{
    const float* x      = (const float*)d_in[0];
    const float* W_attn = (const float*)d_in[1];
    const float* b_attn = (const float*)d_in[2];
    const float* W_proj = (const float*)d_in[3];
    const float* b_proj = (const float*)d_in[4];
    const float* R      = (const float*)d_in[5];
    float* out = (float*)d_out;

    cudaFuncSetAttribute(attn_kernel,
                         cudaFuncAttributeMaxDynamicSharedMemorySize, ATTN_SMEM);

    dim3 g1(3 * Dn / 128, Mn / 128);                 // (24, 128)
    gemm_qkv_kernel<<<g1, 256>>>(x, W_attn, b_attn);

    rope_kernel<<<(BH * Tn * 32 + 255) / 256, 256>>>();

    bucket_kernel<<<BH * Tn / 128, 128>>>(R);

    sort_kernel<<<BH, 1024>>>();

    attn_kernel<<<BH * NCH, 128, ATTN_SMEM>>>();

    dim3 g2(Dn / 128, Mn / 128);                     // (8, 128)
    gemm_out_kernel<<<g2, 256>>>(W_proj, b_proj, out);
}